// round 15
// baseline (speedup 1.0000x reference)
#include <cuda_runtime.h>
#include <cuda_fp16.h>
#include <math.h>
#include <stdint.h>

#define N_NODES_MAX 100000
#define N_EDGES_MAX 1600000
#define F_IN  128
#define HID   128
#define N_CLS 40
#define P2_STRIDE 48          // p2 row padded to 96 B (3 aligned sectors)
#define SCAN_B 1024

// ---------------- scratch (static device globals; zero-initialized) ---------
__device__ __align__(16) float  g_dinv[N_NODES_MAX];
__device__ __align__(16) __half g_h1h [(size_t)N_NODES_MAX * HID];   // x @ W1 (fp16)
__device__ __align__(16) __half g_agg1h[(size_t)N_NODES_MAX * HID];  // Agg(h1) (fp16)
__device__ __align__(16) __half g_p2h [(size_t)N_NODES_MAX * P2_STRIDE];
__device__ __align__(16) int2   g_epair[N_EDGES_MAX];                // converted (src,dst)
__device__ int   g_cnt[N_NODES_MAX];        // zero-init; self-cleaned by scan1
__device__ int   g_cursor[N_NODES_MAX];
__device__ int   g_rowstart[N_NODES_MAX + 1];
__device__ int   g_bsum[128];
__device__ int   g_csr_src[N_EDGES_MAX];
__device__ int   g_idx64 = 1;   // static init; detect only writes 0 -> replay-stable

// ---------------- helpers ----------------------------------------------------
__device__ __forceinline__ int load_idx(const void* ei, long long pos, int is64) {
    return is64 ? (int)((const long long*)ei)[pos] : ((const int*)ei)[pos];
}
__device__ __forceinline__ unsigned to_tf32(float x) {
    float y;
    asm("cvt.rna.tf32.f32 %0, %1;" : "=f"(y) : "f"(x));
    return __float_as_uint(y);
}
__device__ __forceinline__ void acc_h(float4& acc, uint2 raw, float n) {
    float2 f01 = __half22float2(*(__half2*)&raw.x);
    float2 f23 = __half22float2(*(__half2*)&raw.y);
    acc.x += f01.x * n; acc.y += f01.y * n;
    acc.z += f23.x * n; acc.w += f23.y * n;
}

// ---------------- CSR build (4-kernel chain; edge data read once) ------------
__global__ void detect_scan(const int* __restrict__ ei32, int E) {
    int i = threadIdx.x;                       // 1 block, 1024 threads
    long long stride = (2LL * E) / 1024;
    if (stride < 2) stride = 2;
    long long pos = ((long long)i * stride) | 1LL;
    if (pos < 2LL * E && ei32[pos] != 0) g_idx64 = 0;
}

// convert edge_index -> packed int2 pairs AND count in-degrees (single pass)
__global__ void conv_count(const void* __restrict__ ei, int E, int N) {
    int e = blockIdx.x * blockDim.x + threadIdx.x;
    if (e >= E) return;
    int is64 = g_idx64;
    int s = load_idx(ei, e, is64);
    int d = load_idx(ei, (long long)E + e, is64);
    if ((unsigned)s >= (unsigned)N || (unsigned)d >= (unsigned)N) {
        g_epair[e] = make_int2(0, -1);
        return;
    }
    g_epair[e] = make_int2(s, d);
    atomicAdd(&g_cnt[d], 1);
}

// block scan + dinv; SELF-CLEANS g_cnt (restores the zero invariant so the
// zeroing pass is not needed on any call — call 1 relies on static zero-init)
__global__ void scan1(int n) {
    __shared__ int sh[SCAN_B];
    int t = threadIdx.x, b = blockIdx.x;
    int i = b * SCAN_B + t;
    int v = (i < n) ? g_cnt[i] : 0;
    if (i < n) {
        g_dinv[i] = rsqrtf(1.0f + (float)v);
        g_cnt[i] = 0;                          // reset for next replay
    }
    sh[t] = v;
    __syncthreads();
    for (int o = 1; o < SCAN_B; o <<= 1) {
        int x = (t >= o) ? sh[t - o] : 0;
        __syncthreads();
        sh[t] += x;
        __syncthreads();
    }
    if (i < n) g_rowstart[i] = sh[t] - v;
    if (t == SCAN_B - 1) g_bsum[b] = sh[t];
}
__global__ void scan3(int n, int E, int nb) {
    __shared__ int incl[128], excl[128];
    int t = threadIdx.x;
    if (t < 128) {
        int v = (t < nb) ? g_bsum[t] : 0;
        incl[t] = v; excl[t] = v;
    }
    __syncthreads();
    #pragma unroll
    for (int o = 1; o < 128; o <<= 1) {
        int x = (t < 128 && t >= o) ? incl[t - o] : 0;
        __syncthreads();
        if (t < 128) incl[t] += x;
        __syncthreads();
    }
    if (t < 128) excl[t] = incl[t] - excl[t];
    __syncthreads();
    int i = blockIdx.x * blockDim.x + t;
    if (i < n) {
        int v = g_rowstart[i] + excl[i >> 10];
        g_rowstart[i] = v;
        g_cursor[i]   = v;
    }
    if (i == 0) g_rowstart[n] = E;
}
__global__ void csr_fill(int E) {
    int e = blockIdx.x * blockDim.x + threadIdx.x;
    if (e >= E) return;
    int2 p = g_epair[e];
    if (p.y < 0) return;
    g_csr_src[atomicAdd(&g_cursor[p.y], 1)] = p.x;
}

// ---------------- GEMM1: g_h1h = fp16(x @ W1) via tf32 mma.sync -------------
#define AS_STRIDE 132
#define BS_STRIDE 136
#define GEMM1_SMEM ((128 * AS_STRIDE + 128 * BS_STRIDE) * 4)

__global__ __launch_bounds__(256) void gemm1_tf32(const float* __restrict__ A,
                                                  const float* __restrict__ B, int M) {
    extern __shared__ float sm[];
    float* As = sm;
    float* Bs = sm + 128 * AS_STRIDE;
    int tid = threadIdx.x;
    int row0 = blockIdx.x * 128;

    #pragma unroll
    for (int i = 0; i < 16; i++) {
        int lin = tid + 256 * i;
        int r = lin >> 5, kq = lin & 31;
        float4 v = make_float4(0.f, 0.f, 0.f, 0.f);
        if (row0 + r < M) v = *(const float4*)(A + (size_t)(row0 + r) * 128 + kq * 4);
        float* p = As + r * AS_STRIDE + kq * 4;
        p[0] = __uint_as_float(to_tf32(v.x));
        p[1] = __uint_as_float(to_tf32(v.y));
        p[2] = __uint_as_float(to_tf32(v.z));
        p[3] = __uint_as_float(to_tf32(v.w));
    }
    #pragma unroll
    for (int i = 0; i < 16; i++) {
        int lin = tid + 256 * i;
        int k = lin >> 5, nq = lin & 31;
        float4 v = *(const float4*)(B + (size_t)k * 128 + nq * 4);
        float* p = Bs + k * BS_STRIDE + nq * 4;
        p[0] = __uint_as_float(to_tf32(v.x));
        p[1] = __uint_as_float(to_tf32(v.y));
        p[2] = __uint_as_float(to_tf32(v.z));
        p[3] = __uint_as_float(to_tf32(v.w));
    }
    __syncthreads();

    int warp = tid >> 5, lane = tid & 31;
    int wm = (warp & 3) * 32;
    int wn = (warp >> 2) * 64;
    int gid = lane >> 2, tig = lane & 3;

    float acc[2][8][4] = {};

    #pragma unroll
    for (int ks = 0; ks < 16; ks++) {
        int k = ks * 8;
        unsigned af[2][4];
        #pragma unroll
        for (int mt = 0; mt < 2; mt++) {
            const float* base = As + (size_t)(wm + mt * 16 + gid) * AS_STRIDE + k + tig;
            af[mt][0] = __float_as_uint(base[0]);
            af[mt][1] = __float_as_uint(base[8 * AS_STRIDE]);
            af[mt][2] = __float_as_uint(base[4]);
            af[mt][3] = __float_as_uint(base[8 * AS_STRIDE + 4]);
        }
        #pragma unroll
        for (int nt = 0; nt < 8; nt++) {
            int n = wn + nt * 8 + gid;
            unsigned b0 = __float_as_uint(Bs[(size_t)(k + tig) * BS_STRIDE + n]);
            unsigned b1 = __float_as_uint(Bs[(size_t)(k + tig + 4) * BS_STRIDE + n]);
            #pragma unroll
            for (int mt = 0; mt < 2; mt++) {
                asm volatile(
                    "mma.sync.aligned.m16n8k8.row.col.f32.tf32.tf32.f32 "
                    "{%0,%1,%2,%3}, {%4,%5,%6,%7}, {%8,%9}, {%0,%1,%2,%3};\n"
                    : "+f"(acc[mt][nt][0]), "+f"(acc[mt][nt][1]),
                      "+f"(acc[mt][nt][2]), "+f"(acc[mt][nt][3])
                    : "r"(af[mt][0]), "r"(af[mt][1]), "r"(af[mt][2]), "r"(af[mt][3]),
                      "r"(b0), "r"(b1));
            }
        }
    }

    #pragma unroll
    for (int mt = 0; mt < 2; mt++) {
        int r = row0 + wm + mt * 16 + gid;
        #pragma unroll
        for (int nt = 0; nt < 8; nt++) {
            int c = wn + nt * 8 + tig * 2;
            if (r < M)
                *(__half2*)(g_h1h + (size_t)r * 128 + c) =
                    __floats2half2_rn(acc[mt][nt][0], acc[mt][nt][1]);
            if (r + 8 < M)
                *(__half2*)(g_h1h + (size_t)(r + 8) * 128 + c) =
                    __floats2half2_rn(acc[mt][nt][2], acc[mt][nt][3]);
        }
    }
}

// ---------------- agg1: warp-per-node, fp16 rows, fp32 accum (proven form) --
__global__ void agg_f128(int lo, int hi) {
    int node = lo + ((blockIdx.x * blockDim.x + threadIdx.x) >> 5);
    if (node >= hi) return;
    int lane = threadIdx.x & 31;

    float di = g_dinv[node];
    float4 acc = make_float4(0.f, 0.f, 0.f, 0.f);
    acc_h(acc, *(const uint2*)(g_h1h + (size_t)node * HID + lane * 4), di * di);

    int js = g_rowstart[node], je = g_rowstart[node + 1];
    for (int j0 = js; j0 < je; j0 += 32) {
        int rem = je - j0;
        int src = 0; float nrm = 0.0f;
        if (lane < rem) {
            src = g_csr_src[j0 + lane];
            nrm = g_dinv[src] * di;
        }
        int cnt = rem < 32 ? rem : 32;
        int k = 0;
        for (; k + 4 <= cnt; k += 4) {
            int   s[4]; float n[4]; uint2 r[4];
            #pragma unroll
            for (int u = 0; u < 4; u++) {
                s[u] = __shfl_sync(0xFFFFFFFFu, src, k + u);
                n[u] = __shfl_sync(0xFFFFFFFFu, nrm, k + u);
            }
            #pragma unroll
            for (int u = 0; u < 4; u++)
                r[u] = *(const uint2*)(g_h1h + (size_t)s[u] * HID + lane * 4);
            #pragma unroll
            for (int u = 0; u < 4; u++) acc_h(acc, r[u], n[u]);
        }
        for (; k < cnt; k++) {
            int   s = __shfl_sync(0xFFFFFFFFu, src, k);
            float n = __shfl_sync(0xFFFFFFFFu, nrm, k);
            acc_h(acc, *(const uint2*)(g_h1h + (size_t)s * HID + lane * 4), n);
        }
    }
    __half2 h01 = __floats2half2_rn(acc.x, acc.y);
    __half2 h23 = __floats2half2_rn(acc.z, acc.w);
    uint2 packed;
    packed.x = *(unsigned*)&h01;
    packed.y = *(unsigned*)&h23;
    *(uint2*)(g_agg1h + (size_t)node * HID + lane * 4) = packed;
}

// ---------------- GEMM2: g_p2h = fp16(relu(agg1h + b1) @ W2), padded rows ---
#define BM 64
#define BN 64
#define BK 16
__global__ __launch_bounds__(256) void gemm2(const float* __restrict__ B,
                                             int M_lo, int M_hi, int N, int K,
                                             const float* __restrict__ in_bias) {
    __shared__ float As[BK][BM + 1];
    __shared__ float Bs[BK][BN];

    int tid = threadIdx.x;
    int tx = tid & 15, ty = tid >> 4;
    int row0 = M_lo + blockIdx.y * BM;
    int col0 = blockIdx.x * BN;
    float acc[4][4] = {};

    int ka = tid & 15, ma = tid >> 4;
    int nb = tid & 63, kb = tid >> 6;

    for (int k0 = 0; k0 < K; k0 += BK) {
        #pragma unroll
        for (int j = 0; j < 4; j++) {
            int m = ma + 16 * j, gm = row0 + m;
            float v = 0.0f;
            if (gm < M_hi)
                v = fmaxf(__half2float(g_agg1h[(size_t)gm * K + k0 + ka]) +
                          in_bias[k0 + ka], 0.0f);
            As[ka][m] = v;
        }
        #pragma unroll
        for (int j = 0; j < 4; j++) {
            int k = kb + 4 * j, gn = col0 + nb;
            Bs[k][nb] = (gn < N) ? B[(size_t)(k0 + k) * N + gn] : 0.0f;
        }
        __syncthreads();
        #pragma unroll
        for (int kk = 0; kk < BK; kk++) {
            float a[4], b[4];
            #pragma unroll
            for (int i = 0; i < 4; i++) a[i] = As[kk][ty + 16 * i];
            #pragma unroll
            for (int j = 0; j < 4; j++) b[j] = Bs[kk][tx + 16 * j];
            #pragma unroll
            for (int i = 0; i < 4; i++)
                #pragma unroll
                for (int j = 0; j < 4; j++)
                    acc[i][j] += a[i] * b[j];
        }
        __syncthreads();
    }
    #pragma unroll
    for (int i = 0; i < 4; i++) {
        int r = row0 + ty + 16 * i;
        if (r >= M_hi) continue;
        #pragma unroll
        for (int j = 0; j < 4; j++) {
            int c = col0 + tx + 16 * j;
            if (c < N) g_p2h[(size_t)r * P2_STRIDE + c] = __float2half_rn(acc[i][j]);
        }
    }
}

// ---------------- agg2 + log_softmax: fp16 gather (96 B aligned rows) -------
__global__ void agg_f40_lsm(const float* __restrict__ b2, float* __restrict__ out, int N) {
    int warp = (blockIdx.x * blockDim.x + threadIdx.x) >> 5;
    if (warp >= N) return;
    int lane = threadIdx.x & 31;
    bool act = lane < (N_CLS / 2);

    float di = g_dinv[warp];
    float a0 = 0.0f, a1 = 0.0f;
    if (act) {
        float2 f = __half22float2(*(const __half2*)(g_p2h + (size_t)warp * P2_STRIDE + lane * 2));
        float sq = di * di;
        a0 = f.x * sq; a1 = f.y * sq;
    }

    int js = g_rowstart[warp], je = g_rowstart[warp + 1];
    for (int j0 = js; j0 < je; j0 += 32) {
        int rem = je - j0;
        int src = 0; float nrm = 0.0f;
        if (lane < rem) {
            src = g_csr_src[j0 + lane];
            nrm = g_dinv[src] * di;
        }
        int cnt = rem < 32 ? rem : 32;
        int k = 0;
        for (; k + 4 <= cnt; k += 4) {
            int s[4]; float n[4]; unsigned r[4];
            #pragma unroll
            for (int u = 0; u < 4; u++) {
                s[u] = __shfl_sync(0xFFFFFFFFu, src, k + u);
                n[u] = __shfl_sync(0xFFFFFFFFu, nrm, k + u);
            }
            if (act) {
                #pragma unroll
                for (int u = 0; u < 4; u++)
                    r[u] = *(const unsigned*)(g_p2h + (size_t)s[u] * P2_STRIDE + lane * 2);
                #pragma unroll
                for (int u = 0; u < 4; u++) {
                    float2 f = __half22float2(*(__half2*)&r[u]);
                    a0 += f.x * n[u]; a1 += f.y * n[u];
                }
            }
        }
        for (; k < cnt; k++) {
            int   s = __shfl_sync(0xFFFFFFFFu, src, k);
            float n = __shfl_sync(0xFFFFFFFFu, nrm, k);
            if (act) {
                float2 f = __half22float2(*(const __half2*)(g_p2h + (size_t)s * P2_STRIDE + lane * 2));
                a0 += f.x * n; a1 += f.y * n;
            }
        }
    }

    float z0 = -1e30f, z1 = -1e30f;
    if (act) {
        float2 bb = *(const float2*)(b2 + lane * 2);
        z0 = a0 + bb.x; z1 = a1 + bb.y;
    }
    float m = fmaxf(z0, z1);
    #pragma unroll
    for (int o = 16; o; o >>= 1) m = fmaxf(m, __shfl_xor_sync(0xFFFFFFFFu, m, o));
    float s = act ? (expf(z0 - m) + expf(z1 - m)) : 0.0f;
    #pragma unroll
    for (int o = 16; o; o >>= 1) s += __shfl_xor_sync(0xFFFFFFFFu, s, o);
    float lse = m + logf(s);
    if (act)
        *(float2*)(out + (size_t)warp * N_CLS + lane * 2) =
            make_float2(z0 - lse, z1 - lse);
}

// ---------------- launcher (best-known structure: 2-half pipeline) -----------
extern "C" void kernel_launch(void* const* d_in, const int* in_sizes, int n_in,
                              void* d_out, int out_size) {
    const float* x  = (const float*)d_in[0];
    const void*  ei = d_in[1];
    const float* W1 = (const float*)d_in[2];
    const float* b1 = (const float*)d_in[3];
    const float* W2 = (const float*)d_in[4];
    const float* b2 = (const float*)d_in[5];
    float* out = (float*)d_out;

    int N = in_sizes[0] / F_IN;
    int E = in_sizes[1] / 2;
    if (N > N_NODES_MAX) N = N_NODES_MAX;
    if (E > N_EDGES_MAX) E = N_EDGES_MAX;

    const int TB = 256;
    int nb = (N + SCAN_B - 1) / SCAN_B;
    int Nh = ((N / 2) + BM - 1) / BM * BM;
    if (Nh > N) Nh = N;

    cudaFuncSetAttribute(gemm1_tf32,
                         cudaFuncAttributeMaxDynamicSharedMemorySize, GEMM1_SMEM);

    static cudaStream_t s2 = nullptr;
    static cudaEvent_t evF = nullptr, evJ = nullptr, evA = nullptr, evB = nullptr;
    if (!s2) {
        cudaStreamCreateWithFlags(&s2, cudaStreamNonBlocking);
        cudaEventCreateWithFlags(&evF, cudaEventDisableTiming);
        cudaEventCreateWithFlags(&evJ, cudaEventDisableTiming);
        cudaEventCreateWithFlags(&evA, cudaEventDisableTiming);
        cudaEventCreateWithFlags(&evB, cudaEventDisableTiming);
    }

    // fork: CSR build on s2 (4 kernels; counts self-cleaned), GEMM1 on main
    cudaEventRecord(evF, 0);
    cudaStreamWaitEvent(s2, evF, 0);

    detect_scan<<<1, 1024, 0, s2>>>((const int*)ei, E);
    conv_count <<<(E + TB - 1) / TB, TB, 0, s2>>>(ei, E, N);
    scan1<<<nb, SCAN_B, 0, s2>>>(N);
    scan3<<<(N + TB - 1) / TB, TB, 0, s2>>>(N, E, nb);
    csr_fill<<<(E + TB - 1) / TB, TB, 0, s2>>>(E);
    cudaEventRecord(evJ, s2);

    gemm1_tf32<<<(N + 127) / 128, 256, GEMM1_SMEM>>>(x, W1, N);

    // join, then pipeline agg1 halves with gemm2 halves
    cudaStreamWaitEvent(0, evJ, 0);

    agg_f128<<<((long long)Nh * 32 + TB - 1) / TB, TB>>>(0, Nh);
    cudaEventRecord(evA, 0);
    agg_f128<<<((long long)(N - Nh) * 32 + TB - 1) / TB, TB>>>(Nh, N);

    cudaStreamWaitEvent(s2, evA, 0);
    {
        dim3 grid0((N_CLS + BN - 1) / BN, Nh / BM);
        gemm2<<<grid0, TB, 0, s2>>>(W2, 0, Nh, N_CLS, HID, b1);
    }
    cudaEventRecord(evB, s2);
    {
        dim3 grid1((N_CLS + BN - 1) / BN, (N - Nh + BM - 1) / BM);
        if (N > Nh) gemm2<<<grid1, TB>>>(W2, Nh, N, N_CLS, HID, b1);
    }
    cudaStreamWaitEvent(0, evB, 0);

    agg_f40_lsm<<<((long long)N * 32 + TB - 1) / TB, TB>>>(b2, out, N);
}

// round 16
// speedup vs baseline: 1.0012x; 1.0012x over previous
#include <cuda_runtime.h>
#include <cuda_fp16.h>
#include <math.h>
#include <stdint.h>

#define N_NODES_MAX 100000
#define N_EDGES_MAX 1600000
#define F_IN  128
#define HID   128
#define N_CLS 40
#define P2_STRIDE 48          // p2 row padded to 96 B (3 aligned sectors)
#define SCAN_B 1024

// ---------------- scratch (static device globals; zero-initialized) ---------
__device__ __align__(16) float  g_dinv[N_NODES_MAX];
__device__ __align__(16) __half g_h1h [(size_t)N_NODES_MAX * HID];   // x @ W1 (fp16)
__device__ __align__(16) __half g_agg1h[(size_t)N_NODES_MAX * HID];  // Agg(h1) (fp16)
__device__ __align__(16) __half g_p2h [(size_t)N_NODES_MAX * P2_STRIDE];
__device__ __align__(16) int2   g_epair[N_EDGES_MAX];                // (src,dst)
__device__ __align__(16) int    g_epos [N_EDGES_MAX];                // slot within dst row
__device__ int   g_cnt[N_NODES_MAX];        // zero-init; self-cleaned by scan1
__device__ int   g_rowstart[N_NODES_MAX + 1];
__device__ int   g_bsum[128];
__device__ int   g_csr_src[N_EDGES_MAX];
__device__ int   g_idx64 = 1;   // static init; detect only writes 0 -> replay-stable

// ---------------- helpers ----------------------------------------------------
__device__ __forceinline__ int load_idx(const void* ei, long long pos, int is64) {
    return is64 ? (int)((const long long*)ei)[pos] : ((const int*)ei)[pos];
}
__device__ __forceinline__ unsigned to_tf32(float x) {
    float y;
    asm("cvt.rna.tf32.f32 %0, %1;" : "=f"(y) : "f"(x));
    return __float_as_uint(y);
}
__device__ __forceinline__ void acc_h(float4& acc, uint2 raw, float n) {
    float2 f01 = __half22float2(*(__half2*)&raw.x);
    float2 f23 = __half22float2(*(__half2*)&raw.y);
    acc.x += f01.x * n; acc.y += f01.y * n;
    acc.z += f23.x * n; acc.w += f23.y * n;
}

// ---------------- CSR build (atomic position captured in the count pass) -----
__global__ void detect_scan(const int* __restrict__ ei32, int E) {
    int i = threadIdx.x;                       // 1 block, 1024 threads
    long long stride = (2LL * E) / 1024;
    if (stride < 2) stride = 2;
    long long pos = ((long long)i * stride) | 1LL;
    if (pos < 2LL * E && ei32[pos] != 0) g_idx64 = 0;
}

// single pass over edge_index: convert to int2, count in-degree, AND record
// each edge's slot within its destination row (the atomic's return value).
__global__ void conv_count(const void* __restrict__ ei, int E, int N) {
    int e = blockIdx.x * blockDim.x + threadIdx.x;
    if (e >= E) return;
    int is64 = g_idx64;
    int s = load_idx(ei, e, is64);
    int d = load_idx(ei, (long long)E + e, is64);
    if ((unsigned)s >= (unsigned)N || (unsigned)d >= (unsigned)N) {
        g_epair[e] = make_int2(0, -1);
        return;
    }
    g_epair[e] = make_int2(s, d);
    g_epos[e]  = atomicAdd(&g_cnt[d], 1);      // slot = old count (free!)
}

// block scan + dinv; SELF-CLEANS g_cnt (zero invariant for graph replays)
__global__ void scan1(int n) {
    __shared__ int sh[SCAN_B];
    int t = threadIdx.x, b = blockIdx.x;
    int i = b * SCAN_B + t;
    int v = (i < n) ? g_cnt[i] : 0;
    if (i < n) {
        g_dinv[i] = rsqrtf(1.0f + (float)v);
        g_cnt[i] = 0;                          // reset for next replay
    }
    sh[t] = v;
    __syncthreads();
    for (int o = 1; o < SCAN_B; o <<= 1) {
        int x = (t >= o) ? sh[t - o] : 0;
        __syncthreads();
        sh[t] += x;
        __syncthreads();
    }
    if (i < n) g_rowstart[i] = sh[t] - v;
    if (t == SCAN_B - 1) g_bsum[b] = sh[t];
}
__global__ void scan3(int n, int E, int nb) {
    __shared__ int incl[128], excl[128];
    int t = threadIdx.x;
    if (t < 128) {
        int v = (t < nb) ? g_bsum[t] : 0;
        incl[t] = v; excl[t] = v;
    }
    __syncthreads();
    #pragma unroll
    for (int o = 1; o < 128; o <<= 1) {
        int x = (t < 128 && t >= o) ? incl[t - o] : 0;
        __syncthreads();
        if (t < 128) incl[t] += x;
        __syncthreads();
    }
    if (t < 128) excl[t] = incl[t] - excl[t];
    __syncthreads();
    int i = blockIdx.x * blockDim.x + t;
    if (i < n) g_rowstart[i] += excl[i >> 10];
    if (i == 0) g_rowstart[n] = E;
}

// atomic-FREE fill: position was captured during conv_count
__global__ void csr_fill(int E) {
    int e = blockIdx.x * blockDim.x + threadIdx.x;
    if (e >= E) return;
    int2 p = g_epair[e];
    if (p.y < 0) return;
    g_csr_src[g_rowstart[p.y] + g_epos[e]] = p.x;
}

// ---------------- GEMM1: g_h1h = fp16(x @ W1) via tf32 mma.sync -------------
#define AS_STRIDE 132
#define BS_STRIDE 136
#define GEMM1_SMEM ((128 * AS_STRIDE + 128 * BS_STRIDE) * 4)

__global__ __launch_bounds__(256) void gemm1_tf32(const float* __restrict__ A,
                                                  const float* __restrict__ B, int M) {
    extern __shared__ float sm[];
    float* As = sm;
    float* Bs = sm + 128 * AS_STRIDE;
    int tid = threadIdx.x;
    int row0 = blockIdx.x * 128;

    #pragma unroll
    for (int i = 0; i < 16; i++) {
        int lin = tid + 256 * i;
        int r = lin >> 5, kq = lin & 31;
        float4 v = make_float4(0.f, 0.f, 0.f, 0.f);
        if (row0 + r < M) v = *(const float4*)(A + (size_t)(row0 + r) * 128 + kq * 4);
        float* p = As + r * AS_STRIDE + kq * 4;
        p[0] = __uint_as_float(to_tf32(v.x));
        p[1] = __uint_as_float(to_tf32(v.y));
        p[2] = __uint_as_float(to_tf32(v.z));
        p[3] = __uint_as_float(to_tf32(v.w));
    }
    #pragma unroll
    for (int i = 0; i < 16; i++) {
        int lin = tid + 256 * i;
        int k = lin >> 5, nq = lin & 31;
        float4 v = *(const float4*)(B + (size_t)k * 128 + nq * 4);
        float* p = Bs + k * BS_STRIDE + nq * 4;
        p[0] = __uint_as_float(to_tf32(v.x));
        p[1] = __uint_as_float(to_tf32(v.y));
        p[2] = __uint_as_float(to_tf32(v.z));
        p[3] = __uint_as_float(to_tf32(v.w));
    }
    __syncthreads();

    int warp = tid >> 5, lane = tid & 31;
    int wm = (warp & 3) * 32;
    int wn = (warp >> 2) * 64;
    int gid = lane >> 2, tig = lane & 3;

    float acc[2][8][4] = {};

    #pragma unroll
    for (int ks = 0; ks < 16; ks++) {
        int k = ks * 8;
        unsigned af[2][4];
        #pragma unroll
        for (int mt = 0; mt < 2; mt++) {
            const float* base = As + (size_t)(wm + mt * 16 + gid) * AS_STRIDE + k + tig;
            af[mt][0] = __float_as_uint(base[0]);
            af[mt][1] = __float_as_uint(base[8 * AS_STRIDE]);
            af[mt][2] = __float_as_uint(base[4]);
            af[mt][3] = __float_as_uint(base[8 * AS_STRIDE + 4]);
        }
        #pragma unroll
        for (int nt = 0; nt < 8; nt++) {
            int n = wn + nt * 8 + gid;
            unsigned b0 = __float_as_uint(Bs[(size_t)(k + tig) * BS_STRIDE + n]);
            unsigned b1 = __float_as_uint(Bs[(size_t)(k + tig + 4) * BS_STRIDE + n]);
            #pragma unroll
            for (int mt = 0; mt < 2; mt++) {
                asm volatile(
                    "mma.sync.aligned.m16n8k8.row.col.f32.tf32.tf32.f32 "
                    "{%0,%1,%2,%3}, {%4,%5,%6,%7}, {%8,%9}, {%0,%1,%2,%3};\n"
                    : "+f"(acc[mt][nt][0]), "+f"(acc[mt][nt][1]),
                      "+f"(acc[mt][nt][2]), "+f"(acc[mt][nt][3])
                    : "r"(af[mt][0]), "r"(af[mt][1]), "r"(af[mt][2]), "r"(af[mt][3]),
                      "r"(b0), "r"(b1));
            }
        }
    }

    #pragma unroll
    for (int mt = 0; mt < 2; mt++) {
        int r = row0 + wm + mt * 16 + gid;
        #pragma unroll
        for (int nt = 0; nt < 8; nt++) {
            int c = wn + nt * 8 + tig * 2;
            if (r < M)
                *(__half2*)(g_h1h + (size_t)r * 128 + c) =
                    __floats2half2_rn(acc[mt][nt][0], acc[mt][nt][1]);
            if (r + 8 < M)
                *(__half2*)(g_h1h + (size_t)(r + 8) * 128 + c) =
                    __floats2half2_rn(acc[mt][nt][2], acc[mt][nt][3]);
        }
    }
}

// ---------------- agg1: warp-per-node, fp16 rows, fp32 accum (proven form) --
__global__ void agg_f128(int lo, int hi) {
    int node = lo + ((blockIdx.x * blockDim.x + threadIdx.x) >> 5);
    if (node >= hi) return;
    int lane = threadIdx.x & 31;

    float di = g_dinv[node];
    float4 acc = make_float4(0.f, 0.f, 0.f, 0.f);
    acc_h(acc, *(const uint2*)(g_h1h + (size_t)node * HID + lane * 4), di * di);

    int js = g_rowstart[node], je = g_rowstart[node + 1];
    for (int j0 = js; j0 < je; j0 += 32) {
        int rem = je - j0;
        int src = 0; float nrm = 0.0f;
        if (lane < rem) {
            src = g_csr_src[j0 + lane];
            nrm = g_dinv[src] * di;
        }
        int cnt = rem < 32 ? rem : 32;
        int k = 0;
        for (; k + 4 <= cnt; k += 4) {
            int   s[4]; float n[4]; uint2 r[4];
            #pragma unroll
            for (int u = 0; u < 4; u++) {
                s[u] = __shfl_sync(0xFFFFFFFFu, src, k + u);
                n[u] = __shfl_sync(0xFFFFFFFFu, nrm, k + u);
            }
            #pragma unroll
            for (int u = 0; u < 4; u++)
                r[u] = *(const uint2*)(g_h1h + (size_t)s[u] * HID + lane * 4);
            #pragma unroll
            for (int u = 0; u < 4; u++) acc_h(acc, r[u], n[u]);
        }
        for (; k < cnt; k++) {
            int   s = __shfl_sync(0xFFFFFFFFu, src, k);
            float n = __shfl_sync(0xFFFFFFFFu, nrm, k);
            acc_h(acc, *(const uint2*)(g_h1h + (size_t)s * HID + lane * 4), n);
        }
    }
    __half2 h01 = __floats2half2_rn(acc.x, acc.y);
    __half2 h23 = __floats2half2_rn(acc.z, acc.w);
    uint2 packed;
    packed.x = *(unsigned*)&h01;
    packed.y = *(unsigned*)&h23;
    *(uint2*)(g_agg1h + (size_t)node * HID + lane * 4) = packed;
}

// ---------------- GEMM2: g_p2h = fp16(relu(agg1h + b1) @ W2), padded rows ---
#define BM 64
#define BN 64
#define BK 16
__global__ __launch_bounds__(256) void gemm2(const float* __restrict__ B,
                                             int M_lo, int M_hi, int N, int K,
                                             const float* __restrict__ in_bias) {
    __shared__ float As[BK][BM + 1];
    __shared__ float Bs[BK][BN];

    int tid = threadIdx.x;
    int tx = tid & 15, ty = tid >> 4;
    int row0 = M_lo + blockIdx.y * BM;
    int col0 = blockIdx.x * BN;
    float acc[4][4] = {};

    int ka = tid & 15, ma = tid >> 4;
    int nb = tid & 63, kb = tid >> 6;

    for (int k0 = 0; k0 < K; k0 += BK) {
        #pragma unroll
        for (int j = 0; j < 4; j++) {
            int m = ma + 16 * j, gm = row0 + m;
            float v = 0.0f;
            if (gm < M_hi)
                v = fmaxf(__half2float(g_agg1h[(size_t)gm * K + k0 + ka]) +
                          in_bias[k0 + ka], 0.0f);
            As[ka][m] = v;
        }
        #pragma unroll
        for (int j = 0; j < 4; j++) {
            int k = kb + 4 * j, gn = col0 + nb;
            Bs[k][nb] = (gn < N) ? B[(size_t)(k0 + k) * N + gn] : 0.0f;
        }
        __syncthreads();
        #pragma unroll
        for (int kk = 0; kk < BK; kk++) {
            float a[4], b[4];
            #pragma unroll
            for (int i = 0; i < 4; i++) a[i] = As[kk][ty + 16 * i];
            #pragma unroll
            for (int j = 0; j < 4; j++) b[j] = Bs[kk][tx + 16 * j];
            #pragma unroll
            for (int i = 0; i < 4; i++)
                #pragma unroll
                for (int j = 0; j < 4; j++)
                    acc[i][j] += a[i] * b[j];
        }
        __syncthreads();
    }
    #pragma unroll
    for (int i = 0; i < 4; i++) {
        int r = row0 + ty + 16 * i;
        if (r >= M_hi) continue;
        #pragma unroll
        for (int j = 0; j < 4; j++) {
            int c = col0 + tx + 16 * j;
            if (c < N) g_p2h[(size_t)r * P2_STRIDE + c] = __float2half_rn(acc[i][j]);
        }
    }
}

// ---------------- agg2 + log_softmax: fp16 gather (96 B aligned rows) -------
__global__ void agg_f40_lsm(const float* __restrict__ b2, float* __restrict__ out, int N) {
    int warp = (blockIdx.x * blockDim.x + threadIdx.x) >> 5;
    if (warp >= N) return;
    int lane = threadIdx.x & 31;
    bool act = lane < (N_CLS / 2);

    float di = g_dinv[warp];
    float a0 = 0.0f, a1 = 0.0f;
    if (act) {
        float2 f = __half22float2(*(const __half2*)(g_p2h + (size_t)warp * P2_STRIDE + lane * 2));
        float sq = di * di;
        a0 = f.x * sq; a1 = f.y * sq;
    }

    int js = g_rowstart[warp], je = g_rowstart[warp + 1];
    for (int j0 = js; j0 < je; j0 += 32) {
        int rem = je - j0;
        int src = 0; float nrm = 0.0f;
        if (lane < rem) {
            src = g_csr_src[j0 + lane];
            nrm = g_dinv[src] * di;
        }
        int cnt = rem < 32 ? rem : 32;
        int k = 0;
        for (; k + 4 <= cnt; k += 4) {
            int s[4]; float n[4]; unsigned r[4];
            #pragma unroll
            for (int u = 0; u < 4; u++) {
                s[u] = __shfl_sync(0xFFFFFFFFu, src, k + u);
                n[u] = __shfl_sync(0xFFFFFFFFu, nrm, k + u);
            }
            if (act) {
                #pragma unroll
                for (int u = 0; u < 4; u++)
                    r[u] = *(const unsigned*)(g_p2h + (size_t)s[u] * P2_STRIDE + lane * 2);
                #pragma unroll
                for (int u = 0; u < 4; u++) {
                    float2 f = __half22float2(*(__half2*)&r[u]);
                    a0 += f.x * n[u]; a1 += f.y * n[u];
                }
            }
        }
        for (; k < cnt; k++) {
            int   s = __shfl_sync(0xFFFFFFFFu, src, k);
            float n = __shfl_sync(0xFFFFFFFFu, nrm, k);
            if (act) {
                float2 f = __half22float2(*(const __half2*)(g_p2h + (size_t)s * P2_STRIDE + lane * 2));
                a0 += f.x * n; a1 += f.y * n;
            }
        }
    }

    float z0 = -1e30f, z1 = -1e30f;
    if (act) {
        float2 bb = *(const float2*)(b2 + lane * 2);
        z0 = a0 + bb.x; z1 = a1 + bb.y;
    }
    float m = fmaxf(z0, z1);
    #pragma unroll
    for (int o = 16; o; o >>= 1) m = fmaxf(m, __shfl_xor_sync(0xFFFFFFFFu, m, o));
    float s = act ? (expf(z0 - m) + expf(z1 - m)) : 0.0f;
    #pragma unroll
    for (int o = 16; o; o >>= 1) s += __shfl_xor_sync(0xFFFFFFFFu, s, o);
    float lse = m + logf(s);
    if (act)
        *(float2*)(out + (size_t)warp * N_CLS + lane * 2) =
            make_float2(z0 - lse, z1 - lse);
}

// ---------------- launcher (best-known structure: 2-half pipeline) -----------
extern "C" void kernel_launch(void* const* d_in, const int* in_sizes, int n_in,
                              void* d_out, int out_size) {
    const float* x  = (const float*)d_in[0];
    const void*  ei = d_in[1];
    const float* W1 = (const float*)d_in[2];
    const float* b1 = (const float*)d_in[3];
    const float* W2 = (const float*)d_in[4];
    const float* b2 = (const float*)d_in[5];
    float* out = (float*)d_out;

    int N = in_sizes[0] / F_IN;
    int E = in_sizes[1] / 2;
    if (N > N_NODES_MAX) N = N_NODES_MAX;
    if (E > N_EDGES_MAX) E = N_EDGES_MAX;

    const int TB = 256;
    int nb = (N + SCAN_B - 1) / SCAN_B;
    int Nh = ((N / 2) + BM - 1) / BM * BM;
    if (Nh > N) Nh = N;

    cudaFuncSetAttribute(gemm1_tf32,
                         cudaFuncAttributeMaxDynamicSharedMemorySize, GEMM1_SMEM);

    static cudaStream_t s2 = nullptr;
    static cudaEvent_t evF = nullptr, evJ = nullptr, evA = nullptr, evB = nullptr;
    if (!s2) {
        cudaStreamCreateWithFlags(&s2, cudaStreamNonBlocking);
        cudaEventCreateWithFlags(&evF, cudaEventDisableTiming);
        cudaEventCreateWithFlags(&evJ, cudaEventDisableTiming);
        cudaEventCreateWithFlags(&evA, cudaEventDisableTiming);
        cudaEventCreateWithFlags(&evB, cudaEventDisableTiming);
    }

    // fork: CSR build on s2 (atomic-free fill), GEMM1 on main stream
    cudaEventRecord(evF, 0);
    cudaStreamWaitEvent(s2, evF, 0);

    detect_scan<<<1, 1024, 0, s2>>>((const int*)ei, E);
    conv_count <<<(E + TB - 1) / TB, TB, 0, s2>>>(ei, E, N);
    scan1<<<nb, SCAN_B, 0, s2>>>(N);
    scan3<<<(N + TB - 1) / TB, TB, 0, s2>>>(N, E, nb);
    csr_fill<<<(E + TB - 1) / TB, TB, 0, s2>>>(E);
    cudaEventRecord(evJ, s2);

    gemm1_tf32<<<(N + 127) / 128, 256, GEMM1_SMEM>>>(x, W1, N);

    // join, then pipeline agg1 halves with gemm2 halves
    cudaStreamWaitEvent(0, evJ, 0);

    agg_f128<<<((long long)Nh * 32 + TB - 1) / TB, TB>>>(0, Nh);
    cudaEventRecord(evA, 0);
    agg_f128<<<((long long)(N - Nh) * 32 + TB - 1) / TB, TB>>>(Nh, N);

    cudaStreamWaitEvent(s2, evA, 0);
    {
        dim3 grid0((N_CLS + BN - 1) / BN, Nh / BM);
        gemm2<<<grid0, TB, 0, s2>>>(W2, 0, Nh, N_CLS, HID, b1);
    }
    cudaEventRecord(evB, s2);
    {
        dim3 grid1((N_CLS + BN - 1) / BN, (N - Nh + BM - 1) / BM);
        if (N > Nh) gemm2<<<grid1, TB>>>(W2, Nh, N, N_CLS, HID, b1);
    }
    cudaStreamWaitEvent(0, evB, 0);

    agg_f40_lsm<<<((long long)N * 32 + TB - 1) / TB, TB>>>(b2, out, N);
}

// round 17
// speedup vs baseline: 1.1680x; 1.1665x over previous
#include <cuda_runtime.h>
#include <cuda_fp16.h>
#include <math.h>
#include <stdint.h>

#define N_NODES_MAX 100000
#define N_EDGES_MAX 1600000
#define F_IN  128
#define HID   128
#define N_CLS 40
#define P2_STRIDE 48
#define SCAN_B 1024

// ---------------- scratch (static device globals; zero-initialized) ---------
__device__ __align__(16) float  g_dinv[N_NODES_MAX];
__device__ __align__(16) __half g_h1h [(size_t)N_NODES_MAX * HID];
__device__ __align__(16) __half g_agg1h[(size_t)N_NODES_MAX * HID];
__device__ __align__(16) __half g_p2h [(size_t)N_NODES_MAX * P2_STRIDE];
__device__ __align__(16) int2   g_epair[N_EDGES_MAX];
__device__ __align__(16) int    g_epos [N_EDGES_MAX];
__device__ int   g_cnt[N_NODES_MAX];
__device__ int   g_rowstart[N_NODES_MAX + 1];
__device__ int   g_bsum[128];
__device__ int   g_csr_src[N_EDGES_MAX];
__device__ int   g_idx64 = 1;

// ---------------- helpers ----------------------------------------------------
__device__ __forceinline__ int load_idx(const void* ei, long long pos, int is64) {
    return is64 ? (int)((const long long*)ei)[pos] : ((const int*)ei)[pos];
}
__device__ __forceinline__ unsigned to_tf32(float x) {
    float y;
    asm("cvt.rna.tf32.f32 %0, %1;" : "=f"(y) : "f"(x));
    return __float_as_uint(y);
}
__device__ __forceinline__ void acc_h(float4& acc, uint2 raw, float n) {
    float2 f01 = __half22float2(*(__half2*)&raw.x);
    float2 f23 = __half22float2(*(__half2*)&raw.y);
    acc.x += f01.x * n; acc.y += f01.y * n;
    acc.z += f23.x * n; acc.w += f23.y * n;
}

// ---------------- CSR build (fork stream; fully hidden) ----------------------
__global__ void detect_scan(const int* __restrict__ ei32, int E) {
    int i = threadIdx.x;
    long long stride = (2LL * E) / 1024;
    if (stride < 2) stride = 2;
    long long pos = ((long long)i * stride) | 1LL;
    if (pos < 2LL * E && ei32[pos] != 0) g_idx64 = 0;
}
__global__ void conv_count(const void* __restrict__ ei, int E, int N) {
    int e = blockIdx.x * blockDim.x + threadIdx.x;
    if (e >= E) return;
    int is64 = g_idx64;
    int s = load_idx(ei, e, is64);
    int d = load_idx(ei, (long long)E + e, is64);
    if ((unsigned)s >= (unsigned)N || (unsigned)d >= (unsigned)N) {
        g_epair[e] = make_int2(0, -1);
        return;
    }
    g_epair[e] = make_int2(s, d);
    g_epos[e]  = atomicAdd(&g_cnt[d], 1);
}
__global__ void scan1(int n) {
    __shared__ int sh[SCAN_B];
    int t = threadIdx.x, b = blockIdx.x;
    int i = b * SCAN_B + t;
    int v = (i < n) ? g_cnt[i] : 0;
    if (i < n) {
        g_dinv[i] = rsqrtf(1.0f + (float)v);
        g_cnt[i] = 0;
    }
    sh[t] = v;
    __syncthreads();
    for (int o = 1; o < SCAN_B; o <<= 1) {
        int x = (t >= o) ? sh[t - o] : 0;
        __syncthreads();
        sh[t] += x;
        __syncthreads();
    }
    if (i < n) g_rowstart[i] = sh[t] - v;
    if (t == SCAN_B - 1) g_bsum[b] = sh[t];
}
__global__ void scan3(int n, int E, int nb) {
    __shared__ int incl[128], excl[128];
    int t = threadIdx.x;
    if (t < 128) {
        int v = (t < nb) ? g_bsum[t] : 0;
        incl[t] = v; excl[t] = v;
    }
    __syncthreads();
    #pragma unroll
    for (int o = 1; o < 128; o <<= 1) {
        int x = (t < 128 && t >= o) ? incl[t - o] : 0;
        __syncthreads();
        if (t < 128) incl[t] += x;
        __syncthreads();
    }
    if (t < 128) excl[t] = incl[t] - excl[t];
    __syncthreads();
    int i = blockIdx.x * blockDim.x + t;
    if (i < n) g_rowstart[i] += excl[i >> 10];
    if (i == 0) g_rowstart[n] = E;
}
__global__ void csr_fill(int E) {
    int e = blockIdx.x * blockDim.x + threadIdx.x;
    if (e >= E) return;
    int2 p = g_epair[e];
    if (p.y < 0) return;
    g_csr_src[g_rowstart[p.y] + g_epos[e]] = p.x;
}

// ---------------- GEMM1: g_h1h = fp16(x @ W1) via tf32 mma.sync -------------
#define AS_STRIDE 132
#define BS_STRIDE 136
#define GEMM1_SMEM ((128 * AS_STRIDE + 128 * BS_STRIDE) * 4)

__global__ __launch_bounds__(256) void gemm1_tf32(const float* __restrict__ A,
                                                  const float* __restrict__ B, int M) {
    extern __shared__ float sm[];
    float* As = sm;
    float* Bs = sm + 128 * AS_STRIDE;
    int tid = threadIdx.x;
    int row0 = blockIdx.x * 128;

    #pragma unroll
    for (int i = 0; i < 16; i++) {
        int lin = tid + 256 * i;
        int r = lin >> 5, kq = lin & 31;
        float4 v = make_float4(0.f, 0.f, 0.f, 0.f);
        if (row0 + r < M) v = *(const float4*)(A + (size_t)(row0 + r) * 128 + kq * 4);
        float* p = As + r * AS_STRIDE + kq * 4;
        p[0] = __uint_as_float(to_tf32(v.x));
        p[1] = __uint_as_float(to_tf32(v.y));
        p[2] = __uint_as_float(to_tf32(v.z));
        p[3] = __uint_as_float(to_tf32(v.w));
    }
    #pragma unroll
    for (int i = 0; i < 16; i++) {
        int lin = tid + 256 * i;
        int k = lin >> 5, nq = lin & 31;
        float4 v = *(const float4*)(B + (size_t)k * 128 + nq * 4);
        float* p = Bs + k * BS_STRIDE + nq * 4;
        p[0] = __uint_as_float(to_tf32(v.x));
        p[1] = __uint_as_float(to_tf32(v.y));
        p[2] = __uint_as_float(to_tf32(v.z));
        p[3] = __uint_as_float(to_tf32(v.w));
    }
    __syncthreads();

    int warp = tid >> 5, lane = tid & 31;
    int wm = (warp & 3) * 32;
    int wn = (warp >> 2) * 64;
    int gid = lane >> 2, tig = lane & 3;

    float acc[2][8][4] = {};

    #pragma unroll
    for (int ks = 0; ks < 16; ks++) {
        int k = ks * 8;
        unsigned af[2][4];
        #pragma unroll
        for (int mt = 0; mt < 2; mt++) {
            const float* base = As + (size_t)(wm + mt * 16 + gid) * AS_STRIDE + k + tig;
            af[mt][0] = __float_as_uint(base[0]);
            af[mt][1] = __float_as_uint(base[8 * AS_STRIDE]);
            af[mt][2] = __float_as_uint(base[4]);
            af[mt][3] = __float_as_uint(base[8 * AS_STRIDE + 4]);
        }
        #pragma unroll
        for (int nt = 0; nt < 8; nt++) {
            int n = wn + nt * 8 + gid;
            unsigned b0 = __float_as_uint(Bs[(size_t)(k + tig) * BS_STRIDE + n]);
            unsigned b1 = __float_as_uint(Bs[(size_t)(k + tig + 4) * BS_STRIDE + n]);
            #pragma unroll
            for (int mt = 0; mt < 2; mt++) {
                asm volatile(
                    "mma.sync.aligned.m16n8k8.row.col.f32.tf32.tf32.f32 "
                    "{%0,%1,%2,%3}, {%4,%5,%6,%7}, {%8,%9}, {%0,%1,%2,%3};\n"
                    : "+f"(acc[mt][nt][0]), "+f"(acc[mt][nt][1]),
                      "+f"(acc[mt][nt][2]), "+f"(acc[mt][nt][3])
                    : "r"(af[mt][0]), "r"(af[mt][1]), "r"(af[mt][2]), "r"(af[mt][3]),
                      "r"(b0), "r"(b1));
            }
        }
    }

    #pragma unroll
    for (int mt = 0; mt < 2; mt++) {
        int r = row0 + wm + mt * 16 + gid;
        #pragma unroll
        for (int nt = 0; nt < 8; nt++) {
            int c = wn + nt * 8 + tig * 2;
            if (r < M)
                *(__half2*)(g_h1h + (size_t)r * 128 + c) =
                    __floats2half2_rn(acc[mt][nt][0], acc[mt][nt][1]);
            if (r + 8 < M)
                *(__half2*)(g_h1h + (size_t)(r + 8) * 128 + c) =
                    __floats2half2_rn(acc[mt][nt][2], acc[mt][nt][3]);
        }
    }
}

// ---------------- agg1: warp-per-node, fp16 rows, fp32 accum (proven) -------
__global__ void agg_f128(int N) {
    int node = (blockIdx.x * blockDim.x + threadIdx.x) >> 5;
    if (node >= N) return;
    int lane = threadIdx.x & 31;

    float di = g_dinv[node];
    float4 acc = make_float4(0.f, 0.f, 0.f, 0.f);
    acc_h(acc, *(const uint2*)(g_h1h + (size_t)node * HID + lane * 4), di * di);

    int js = g_rowstart[node], je = g_rowstart[node + 1];
    for (int j0 = js; j0 < je; j0 += 32) {
        int rem = je - j0;
        int src = 0; float nrm = 0.0f;
        if (lane < rem) {
            src = g_csr_src[j0 + lane];
            nrm = g_dinv[src] * di;
        }
        int cnt = rem < 32 ? rem : 32;
        int k = 0;
        for (; k + 4 <= cnt; k += 4) {
            int   s[4]; float n[4]; uint2 r[4];
            #pragma unroll
            for (int u = 0; u < 4; u++) {
                s[u] = __shfl_sync(0xFFFFFFFFu, src, k + u);
                n[u] = __shfl_sync(0xFFFFFFFFu, nrm, k + u);
            }
            #pragma unroll
            for (int u = 0; u < 4; u++)
                r[u] = *(const uint2*)(g_h1h + (size_t)s[u] * HID + lane * 4);
            #pragma unroll
            for (int u = 0; u < 4; u++) acc_h(acc, r[u], n[u]);
        }
        for (; k < cnt; k++) {
            int   s = __shfl_sync(0xFFFFFFFFu, src, k);
            float n = __shfl_sync(0xFFFFFFFFu, nrm, k);
            acc_h(acc, *(const uint2*)(g_h1h + (size_t)s * HID + lane * 4), n);
        }
    }
    __half2 h01 = __floats2half2_rn(acc.x, acc.y);
    __half2 h23 = __floats2half2_rn(acc.z, acc.w);
    uint2 packed;
    packed.x = *(unsigned*)&h01;
    packed.y = *(unsigned*)&h23;
    *(uint2*)(g_agg1h + (size_t)node * HID + lane * 4) = packed;
}

// ---------------- GEMM2 (tensor): p2h = fp16(relu(agg1h+b1) @ W2), tf32 -----
// M=128/block, K=128, N=40 padded to 64. Same fragment recipe as gemm1.
#define AS2_STRIDE 132
#define BS2_STRIDE 72         // %32 == 8 -> conflict-free B fragments
#define GEMM2_SMEM ((128 * AS2_STRIDE + 128 * BS2_STRIDE) * 4)

__global__ __launch_bounds__(256) void gemm2_tf32(const float* __restrict__ W2,
                                                  const float* __restrict__ b1, int M) {
    extern __shared__ float sm2[];
    float* As = sm2;
    float* Bs = sm2 + 128 * AS2_STRIDE;
    int tid = threadIdx.x;
    int row0 = blockIdx.x * 128;

    // stage A = tf32(relu(agg1h + b1))
    #pragma unroll
    for (int i = 0; i < 16; i++) {
        int lin = tid + 256 * i;          // 0..4095
        int r = lin >> 5, kq = lin & 31;  // row, 4-col group
        int gm = row0 + r;
        float4 v = make_float4(0.f, 0.f, 0.f, 0.f);
        if (gm < M) {
            uint2 raw = *(const uint2*)(g_agg1h + (size_t)gm * 128 + kq * 4);
            float2 f01 = __half22float2(*(__half2*)&raw.x);
            float2 f23 = __half22float2(*(__half2*)&raw.y);
            const float* bb = b1 + kq * 4;
            v.x = fmaxf(f01.x + bb[0], 0.0f);
            v.y = fmaxf(f01.y + bb[1], 0.0f);
            v.z = fmaxf(f23.x + bb[2], 0.0f);
            v.w = fmaxf(f23.y + bb[3], 0.0f);
        }
        float* p = As + r * AS2_STRIDE + kq * 4;
        p[0] = __uint_as_float(to_tf32(v.x));
        p[1] = __uint_as_float(to_tf32(v.y));
        p[2] = __uint_as_float(to_tf32(v.z));
        p[3] = __uint_as_float(to_tf32(v.w));
    }
    // stage B: W2 [128 x 40] -> [128 x 64] zero-padded, tf32
    #pragma unroll
    for (int i = 0; i < 32; i++) {        // 128*64/256
        int lin = tid + 256 * i;
        int k = lin >> 6, n = lin & 63;
        float v = (n < N_CLS) ? W2[k * N_CLS + n] : 0.0f;
        Bs[k * BS2_STRIDE + n] = __uint_as_float(to_tf32(v));
    }
    __syncthreads();

    int warp = tid >> 5, lane = tid & 31;
    int wm = warp * 16;                   // 8 warps x 16 rows = 128
    int gid = lane >> 2, tig = lane & 3;

    float acc[8][4] = {};

    #pragma unroll
    for (int ks = 0; ks < 16; ks++) {
        int k = ks * 8;
        const float* base = As + (size_t)(wm + gid) * AS2_STRIDE + k + tig;
        unsigned a0 = __float_as_uint(base[0]);
        unsigned a1 = __float_as_uint(base[8 * AS2_STRIDE]);
        unsigned a2 = __float_as_uint(base[4]);
        unsigned a3 = __float_as_uint(base[8 * AS2_STRIDE + 4]);
        #pragma unroll
        for (int nt = 0; nt < 8; nt++) {
            int n = nt * 8 + gid;
            unsigned b0 = __float_as_uint(Bs[(size_t)(k + tig) * BS2_STRIDE + n]);
            unsigned b1r = __float_as_uint(Bs[(size_t)(k + tig + 4) * BS2_STRIDE + n]);
            asm volatile(
                "mma.sync.aligned.m16n8k8.row.col.f32.tf32.tf32.f32 "
                "{%0,%1,%2,%3}, {%4,%5,%6,%7}, {%8,%9}, {%0,%1,%2,%3};\n"
                : "+f"(acc[nt][0]), "+f"(acc[nt][1]), "+f"(acc[nt][2]), "+f"(acc[nt][3])
                : "r"(a0), "r"(a1), "r"(a2), "r"(a3), "r"(b0), "r"(b1r));
        }
    }

    #pragma unroll
    for (int nt = 0; nt < 5; nt++) {      // nt >= 5 -> cols >= 40 (padding)
        int c = nt * 8 + tig * 2;
        if (c >= N_CLS) continue;
        int r = row0 + wm + gid;
        if (r < M)
            *(__half2*)(g_p2h + (size_t)r * P2_STRIDE + c) =
                __floats2half2_rn(acc[nt][0], acc[nt][1]);
        if (r + 8 < M)
            *(__half2*)(g_p2h + (size_t)(r + 8) * P2_STRIDE + c) =
                __floats2half2_rn(acc[nt][2], acc[nt][3]);
    }
}

// ---------------- agg2 + log_softmax: fp16 gather (96 B aligned rows) -------
__global__ void agg_f40_lsm(const float* __restrict__ b2, float* __restrict__ out, int N) {
    int warp = (blockIdx.x * blockDim.x + threadIdx.x) >> 5;
    if (warp >= N) return;
    int lane = threadIdx.x & 31;
    bool act = lane < (N_CLS / 2);

    float di = g_dinv[warp];
    float a0 = 0.0f, a1 = 0.0f;
    if (act) {
        float2 f = __half22float2(*(const __half2*)(g_p2h + (size_t)warp * P2_STRIDE + lane * 2));
        float sq = di * di;
        a0 = f.x * sq; a1 = f.y * sq;
    }

    int js = g_rowstart[warp], je = g_rowstart[warp + 1];
    for (int j0 = js; j0 < je; j0 += 32) {
        int rem = je - j0;
        int src = 0; float nrm = 0.0f;
        if (lane < rem) {
            src = g_csr_src[j0 + lane];
            nrm = g_dinv[src] * di;
        }
        int cnt = rem < 32 ? rem : 32;
        int k = 0;
        for (; k + 4 <= cnt; k += 4) {
            int s[4]; float n[4]; unsigned r[4];
            #pragma unroll
            for (int u = 0; u < 4; u++) {
                s[u] = __shfl_sync(0xFFFFFFFFu, src, k + u);
                n[u] = __shfl_sync(0xFFFFFFFFu, nrm, k + u);
            }
            if (act) {
                #pragma unroll
                for (int u = 0; u < 4; u++)
                    r[u] = *(const unsigned*)(g_p2h + (size_t)s[u] * P2_STRIDE + lane * 2);
                #pragma unroll
                for (int u = 0; u < 4; u++) {
                    float2 f = __half22float2(*(__half2*)&r[u]);
                    a0 += f.x * n[u]; a1 += f.y * n[u];
                }
            }
        }
        for (; k < cnt; k++) {
            int   s = __shfl_sync(0xFFFFFFFFu, src, k);
            float n = __shfl_sync(0xFFFFFFFFu, nrm, k);
            if (act) {
                float2 f = __half22float2(*(const __half2*)(g_p2h + (size_t)s * P2_STRIDE + lane * 2));
                a0 += f.x * n; a1 += f.y * n;
            }
        }
    }

    float z0 = -1e30f, z1 = -1e30f;
    if (act) {
        float2 bb = *(const float2*)(b2 + lane * 2);
        z0 = a0 + bb.x; z1 = a1 + bb.y;
    }
    float m = fmaxf(z0, z1);
    #pragma unroll
    for (int o = 16; o; o >>= 1) m = fmaxf(m, __shfl_xor_sync(0xFFFFFFFFu, m, o));
    float s = act ? (expf(z0 - m) + expf(z1 - m)) : 0.0f;
    #pragma unroll
    for (int o = 16; o; o >>= 1) s += __shfl_xor_sync(0xFFFFFFFFu, s, o);
    float lse = m + logf(s);
    if (act)
        *(float2*)(out + (size_t)warp * N_CLS + lane * 2) =
            make_float2(z0 - lse, z1 - lse);
}

// ---------------- launcher ----------------------------------------------------
extern "C" void kernel_launch(void* const* d_in, const int* in_sizes, int n_in,
                              void* d_out, int out_size) {
    const float* x  = (const float*)d_in[0];
    const void*  ei = d_in[1];
    const float* W1 = (const float*)d_in[2];
    const float* b1 = (const float*)d_in[3];
    const float* W2 = (const float*)d_in[4];
    const float* b2 = (const float*)d_in[5];
    float* out = (float*)d_out;

    int N = in_sizes[0] / F_IN;
    int E = in_sizes[1] / 2;
    if (N > N_NODES_MAX) N = N_NODES_MAX;
    if (E > N_EDGES_MAX) E = N_EDGES_MAX;

    const int TB = 256;
    int nb = (N + SCAN_B - 1) / SCAN_B;

    cudaFuncSetAttribute(gemm1_tf32,
                         cudaFuncAttributeMaxDynamicSharedMemorySize, GEMM1_SMEM);
    cudaFuncSetAttribute(gemm2_tf32,
                         cudaFuncAttributeMaxDynamicSharedMemorySize, GEMM2_SMEM);

    static cudaStream_t s2 = nullptr;
    static cudaEvent_t evF = nullptr, evJ = nullptr;
    if (!s2) {
        cudaStreamCreateWithFlags(&s2, cudaStreamNonBlocking);
        cudaEventCreateWithFlags(&evF, cudaEventDisableTiming);
        cudaEventCreateWithFlags(&evJ, cudaEventDisableTiming);
    }

    // fork: CSR build on s2 (hidden under gemm1), GEMM1 on main stream
    cudaEventRecord(evF, 0);
    cudaStreamWaitEvent(s2, evF, 0);

    detect_scan<<<1, 1024, 0, s2>>>((const int*)ei, E);
    conv_count <<<(E + TB - 1) / TB, TB, 0, s2>>>(ei, E, N);
    scan1<<<nb, SCAN_B, 0, s2>>>(N);
    scan3<<<(N + TB - 1) / TB, TB, 0, s2>>>(N, E, nb);
    csr_fill<<<(E + TB - 1) / TB, TB, 0, s2>>>(E);
    cudaEventRecord(evJ, s2);

    gemm1_tf32<<<(N + 127) / 128, 256, GEMM1_SMEM>>>(x, W1, N);

    // join, then simple serial tail (gemm2 is now tensor-core cheap)
    cudaStreamWaitEvent(0, evJ, 0);

    agg_f128  <<<((long long)N * 32 + TB - 1) / TB, TB>>>(N);
    gemm2_tf32<<<(N + 127) / 128, 256, GEMM2_SMEM>>>(W2, b1, N);
    agg_f40_lsm<<<((long long)N * 32 + TB - 1) / TB, TB>>>(b2, out, N);
}